// round 13
// baseline (speedup 1.0000x reference)
#include <cuda_runtime.h>

// ConvQuadInterp3d over x:(2,1,8,512,512) fp32.
// Output = coords_max (B,1,3,D,H,W) then y_max (B,1,D,H,W), fp32.
// Each thread: 2 consecutive w (float2 I/O), fully-unrolled d loop.
// Per-plane compressed window: M[4] (mid row), dv[4]=bot-top, sv[4]=bot+top,
// NMS triples t[2]; prev plane keeps only MP[4], dvP(center pair), tP[2].
// Derivative algebra bit-identical to the reference factoring.

#define Dd 8
#define Hh 512
#define Ww 512
#define Bb 2
#define PLANE (Hh * Ww)

// Load 4 consecutive values covering [w0-1, w0+2] with replicate clamp.
__device__ __forceinline__ void load_row4(const float* __restrict__ row, int w0,
                                          bool wL, bool wR, float* v) {
    const float2 q = __ldg(reinterpret_cast<const float2*>(row + w0));
    v[1] = q.x; v[2] = q.y;
    v[0] = wL ? q.x : __ldg(row + w0 - 1);
    v[3] = wR ? q.y : __ldg(row + w0 + 2);
}

// Load plane and compress: M (mid row), dv = B - T, sv = B + T, t = NMS triples.
__device__ __forceinline__ void load_plane(const float* __restrict__ pl,
                                           int otop, int omid, int obot,
                                           int w0, bool wL, bool wR,
                                           float* M, float* dv, float* sv, float* t) {
    float T[4], B[4];
    load_row4(pl + otop, w0, wL, wR, T);
    load_row4(pl + omid, w0, wL, wR, M);
    load_row4(pl + obot, w0, wL, wR, B);
    float c[4];
#pragma unroll
    for (int i = 0; i < 4; i++) {
        c[i]  = fmaxf(T[i], fmaxf(M[i], B[i]));
        dv[i] = B[i] - T[i];
        sv[i] = B[i] + T[i];
    }
    const float mid = fmaxf(c[1], c[2]);
    t[0] = fmaxf(c[0], mid);
    t[1] = fmaxf(mid, c[3]);
}

__global__ void __launch_bounds__(128, 6)
conv_quad_interp3d_kernel(const float* __restrict__ x, float* __restrict__ out) {
    const int w0 = (blockIdx.x * 32 + threadIdx.x) * 2;  // multiple of 2
    const int h  = blockIdx.y * 4 + threadIdx.y;
    const int b  = blockIdx.z;

    const bool wL = (w0 == 0), wR = (w0 == Ww - 2);
    const int hm = max(h - 1, 0), hp = min(h + 1, Hh - 1);
    const int otop = hm * Ww, omid = h * Ww, obot = hp * Ww;
    const float hf = (float)h, wf = (float)w0;

    const float* xb = x + b * Dd * PLANE;

    // Window: P (prev: mid row + center dv pair + triples), C, N (full).
    float MP[4], dvP1, dvP2, tP[2];
    float MC[4], dvC[4], svC[4], tC[2];
    float MN[4], dvN[4], svN[4], tN[2];

    load_plane(xb + 0 * PLANE, otop, omid, obot, w0, wL, wR, MC, dvC, svC, tC);
#pragma unroll
    for (int i = 0; i < 4; i++) MP[i] = MC[i];
    dvP1 = dvC[1]; dvP2 = dvC[2];
    tP[0] = tC[0]; tP[1] = tC[1];                 // replicate pad d = -1
    load_plane(xb + 1 * PLANE, otop, omid, obot, w0, wL, wR, MN, dvN, svN, tN);

    const int hw = h * Ww + w0;
    float* pD = out + (b * 3 + 0) * Dd * PLANE + hw;
    float* pW = pD + Dd * PLANE;
    float* pH = pW + Dd * PLANE;
    float* pY = out + (Bb * 3) * Dd * PLANE + b * Dd * PLANE + hw;

#pragma unroll
    for (int d = 0; d < Dd; d++) {
        float rD[2], rW[2], rH[2], rY[2];

#pragma unroll
        for (int j = 0; j < 2; j++) {
            const float c = MC[j + 1];
            const float dvPj = (j == 0) ? dvP1 : dvP2;

            // NMS: max over 27 = max of 3 cached per-plane triple-maxes.
            const float m = fmaxf(tP[j], fmaxf(tC[j], tN[j]));
            const bool nms = (c == m);

            // Gradients (central diff / 2, replicate pad)
            const float gx = 0.5f * (MC[j + 2] - MC[j]);
            const float gy = 0.5f * dvC[j + 1];
            const float gs = 0.5f * (MN[j + 1] - MP[j + 1]);

            // Hessian (cross terms * 0.25)
            const float axx = MC[j] + MC[j + 2] - 2.0f * c;
            const float ayy = svC[j + 1] - 2.0f * c;
            const float ass = MP[j + 1] + MN[j + 1] - 2.0f * c;
            const float axy = 0.25f * (dvC[j + 2] - dvC[j]);
            const float ays = 0.25f * (dvN[j + 1] - dvPj);
            const float axs = 0.25f * ((MN[j + 2] - MP[j + 2]) - (MN[j] - MP[j]));

            // Symmetric 3x3 solve via adjugate (Cramer)
            const float c00 = ayy * ass - ays * ays;
            const float c01 = axs * ays - axy * ass;
            const float c02 = axy * ays - axs * ayy;
            const float det = axx * c00 + axy * c01 + axs * c02;
            const bool keep = nms && (det != 0.0f);

            float rx = 0.0f, ry = 0.0f, rs = 0.0f;
            if (keep) {
                const float inv = 1.0f / det;
                const float c11 = axx * ass - axs * axs;
                const float c12 = axy * axs - axx * ays;
                const float c22 = axx * ayy - axy * axy;
                rx = -(c00 * gx + c01 * gy + c02 * gs) * inv;
                ry = -(c01 * gx + c11 * gy + c12 * gs) * inv;
                rs = -(c02 * gx + c12 * gy + c22 * gs) * inv;
                const float big = fmaxf(fabsf(rx), fmaxf(fabsf(ry), fabsf(rs)));
                if (big > 0.7f) { rx = 0.0f; ry = 0.0f; rs = 0.0f; }
            }

            const float dyv = 0.5f * (gx * rx + gy * ry + gs * rs);
            rY[j] = c + dyv + (keep ? 10.0f : 0.0f);
            // grid channels (d, w, h) + flipped refinement (s, y, x)
            rD[j] = (float)d + rs;
            rW[j] = (wf + (float)j) + ry;
            rH[j] = hf + rx;
        }

        *reinterpret_cast<float2*>(pD + d * PLANE) = make_float2(rD[0], rD[1]);
        *reinterpret_cast<float2*>(pW + d * PLANE) = make_float2(rW[0], rW[1]);
        *reinterpret_cast<float2*>(pH + d * PLANE) = make_float2(rH[0], rH[1]);
        *reinterpret_cast<float2*>(pY + d * PLANE) = make_float2(rY[0], rY[1]);

        if (d < Dd - 1) {
            // Shift window (free renames in the unrolled loop)
            dvP1 = dvC[1]; dvP2 = dvC[2];
            tP[0] = tC[0]; tP[1] = tC[1];
#pragma unroll
            for (int i = 0; i < 4; i++) {
                MP[i] = MC[i];
                MC[i] = MN[i]; dvC[i] = dvN[i]; svC[i] = svN[i];
            }
            tC[0] = tN[0]; tC[1] = tN[1];
            if (d + 2 < Dd) {
                load_plane(xb + (d + 2) * PLANE, otop, omid, obot, w0, wL, wR,
                           MN, dvN, svN, tN);
            }
            // else: N keeps plane 7 == replicate pad at d = 8.
        }
    }
}

extern "C" void kernel_launch(void* const* d_in, const int* in_sizes, int n_in,
                              void* d_out, int out_size) {
    const float* x = (const float*)d_in[0];
    float* out = (float*)d_out;
    dim3 block(32, 4, 1);
    dim3 grid(Ww / (32 * 2), Hh / 4, Bb);  // (8, 128, 2) = 2048 blocks
    conv_quad_interp3d_kernel<<<grid, block>>>(x, out);
}

// round 14
// speedup vs baseline: 1.9350x; 1.9350x over previous
#include <cuda_runtime.h>

// ConvQuadInterp3d over x:(2,1,8,512,512) fp32.
// Output = coords_max (B,1,3,D,H,W) then y_max (B,1,D,H,W), fp32.
// One thread per (b,h,w); fully-unrolled d loop. Combines:
//  - lean rolling window (prev plane = 5 cross values + whole-plane NMS max,
//    C/N = 9 values + plane max) for low register pressure,
//  - depth-2 software pipeline: Q holds plane d+2's loads issued one full
//    iteration before consumption (hides L2 latency),
//  - R3-style per-call row addressing (known-good codegen).

#define Dd 8
#define Hh 512
#define Ww 512
#define Bb 2
#define PLANE (Hh * Ww)

__device__ __forceinline__ void load9(const float* __restrict__ x, int base,
                                      int hm, int h0, int hp,
                                      int wm, int w0, int wp, float* p) {
    const float* r0 = x + base + hm * Ww;
    const float* r1 = x + base + h0 * Ww;
    const float* r2 = x + base + hp * Ww;
    p[0] = __ldg(r0 + wm); p[1] = __ldg(r0 + w0); p[2] = __ldg(r0 + wp);
    p[3] = __ldg(r1 + wm); p[4] = __ldg(r1 + w0); p[5] = __ldg(r1 + wp);
    p[6] = __ldg(r2 + wm); p[7] = __ldg(r2 + w0); p[8] = __ldg(r2 + wp);
}

__device__ __forceinline__ float max9(const float* p) {
    float m0 = fmaxf(p[0], fmaxf(p[3], p[6]));
    float m1 = fmaxf(p[1], fmaxf(p[4], p[7]));
    float m2 = fmaxf(p[2], fmaxf(p[5], p[8]));
    return fmaxf(m0, fmaxf(m1, m2));
}

__global__ void __launch_bounds__(128, 7)
conv_quad_interp3d_kernel(const float* __restrict__ x, float* __restrict__ out) {
    const int w = blockIdx.x * 32 + threadIdx.x;
    const int h = blockIdx.y * 4 + threadIdx.y;
    const int b = blockIdx.z;

    const int wm = max(w - 1, 0), wp = min(w + 1, Ww - 1);
    const int hm = max(h - 1, 0), hp = min(h + 1, Hh - 1);
    const int xbase = b * Dd * PLANE;
    const float wf = (float)w, hf = (float)h;

    // Window: prev = 5 cross values + plane max; C/N = 9 + plane max; Q in flight.
    float pm1, pm3, pm4, pm5, pm7, mP;
    float C[9], N[9], Q[9], mC, mN;

    load9(x, xbase + 0 * PLANE, hm, h, hp, wm, w, wp, C);
    mC = max9(C);
    pm1 = C[1]; pm3 = C[3]; pm4 = C[4]; pm5 = C[5]; pm7 = C[7];  // replicate d=-1
    mP = mC;
    load9(x, xbase + 1 * PLANE, hm, h, hp, wm, w, wp, N);
    mN = max9(N);
    load9(x, xbase + 2 * PLANE, hm, h, hp, wm, w, wp, Q);  // in flight over iter 0

    const int hw = h * Ww + w;
    float* pD = out + (b * 3 + 0) * Dd * PLANE + hw;
    float* pW = out + (b * 3 + 1) * Dd * PLANE + hw;
    float* pH = out + (b * 3 + 2) * Dd * PLANE + hw;
    float* pY = out + (Bb * 3) * Dd * PLANE + b * Dd * PLANE + hw;

#pragma unroll
    for (int d = 0; d < Dd; d++) {
        const float c = C[4];

        // NMS: max over 27 = max of 3 cached whole-plane 3x3 maxima.
        const float m = fmaxf(mP, fmaxf(mC, mN));
        const bool nms = (c == m);

        // Gradients (central diff / 2, replicate pad)
        const float gx = 0.5f * (C[5] - C[3]);
        const float gy = 0.5f * (C[7] - C[1]);
        const float gs = 0.5f * (N[4] - pm4);

        // Hessian (cross terms * 0.25 per reference)
        const float axx = C[3] + C[5] - 2.0f * c;
        const float ayy = C[1] + C[7] - 2.0f * c;
        const float ass = pm4 + N[4] - 2.0f * c;
        const float axy = 0.25f * (C[0] + C[8] - C[6] - C[2]);
        const float ays = 0.25f * (pm1 + N[7] - N[1] - pm7);
        const float axs = 0.25f * (pm3 + N[5] - N[3] - pm5);

        // Symmetric 3x3 solve via adjugate (Cramer)
        const float c00 = ayy * ass - ays * ays;
        const float c01 = axs * ays - axy * ass;
        const float c02 = axy * ays - axs * ayy;
        const float det = axx * c00 + axy * c01 + axs * c02;
        const bool keep = nms && (det != 0.0f);

        float rx = 0.0f, ry = 0.0f, rs = 0.0f;
        if (keep) {
            const float inv = 1.0f / det;
            const float c11 = axx * ass - axs * axs;
            const float c12 = axy * axs - axx * ays;
            const float c22 = axx * ayy - axy * axy;
            rx = -(c00 * gx + c01 * gy + c02 * gs) * inv;
            ry = -(c01 * gx + c11 * gy + c12 * gs) * inv;
            rs = -(c02 * gx + c12 * gy + c22 * gs) * inv;
            const float big = fmaxf(fabsf(rx), fmaxf(fabsf(ry), fabsf(rs)));
            if (big > 0.7f) { rx = 0.0f; ry = 0.0f; rs = 0.0f; }
        }

        const float dyv = 0.5f * (gx * rx + gy * ry + gs * rs);
        const float y = c + dyv + (keep ? 10.0f : 0.0f);

        // coords channels: grid(d, w, h) + flipped refinement (s, y, x)
        pD[d * PLANE] = (float)d + rs;
        pW[d * PLANE] = wf + ry;
        pH[d * PLANE] = hf + rx;
        pY[d * PLANE] = y;

        if (d < Dd - 1) {
            pm1 = C[1]; pm3 = C[3]; pm4 = C[4]; pm5 = C[5]; pm7 = C[7];
            mP = mC;
#pragma unroll
            for (int i = 0; i < 9; i++) C[i] = N[i];
            mC = mN;
#pragma unroll
            for (int i = 0; i < 9; i++) N[i] = Q[i];
            mN = max9(N);
            // Prefetch plane d+3 into Q, consumed one iteration later.
            // For d > 4 no load: Q (and thus N) retains plane 7 = replicate pad.
            if (d + 3 < Dd) {
                load9(x, xbase + (d + 3) * PLANE, hm, h, hp, wm, w, wp, Q);
            }
        }
    }
}

extern "C" void kernel_launch(void* const* d_in, const int* in_sizes, int n_in,
                              void* d_out, int out_size) {
    const float* x = (const float*)d_in[0];
    float* out = (float*)d_out;
    dim3 block(32, 4, 1);
    dim3 grid(Ww / 32, Hh / 4, Bb);  // (16, 128, 2)
    conv_quad_interp3d_kernel<<<grid, block>>>(x, out);
}

// round 15
// speedup vs baseline: 2.2443x; 1.1599x over previous
#include <cuda_runtime.h>

// ConvQuadInterp3d over x:(2,1,8,512,512) fp32.
// Output = coords_max (B,1,3,D,H,W) then y_max (B,1,D,H,W), fp32.
// Block = 32x4 tile. ALL 8 planes' halo (6x34x8 = 1632 floats, 6.4KB) staged
// into SMEM in one prologue (2 clamped LDG/thread/plane), ONE __syncthreads(),
// then R3's rolling-window mainloop with window reads as LDS [reg + imm]
// (29 cyc) instead of LDG->L2 (~240 cyc). No per-iteration sync machinery.

#define Dd 8
#define Hh 512
#define Ww 512
#define Bb 2
#define PLANE (Hh * Ww)
#define TW 32
#define TH 4
#define SROW 34
#define SPLN (6 * SROW)    // 204 floats per staged plane

__global__ void __launch_bounds__(128, 7)
conv_quad_interp3d_kernel(const float* __restrict__ x, float* __restrict__ out) {
    __shared__ float sm[Dd * SPLN];   // 1632 floats = 6528 B

    const int tdx = threadIdx.x, tdy = threadIdx.y;
    const int tid = tdy * TW + tdx;
    const int w0 = blockIdx.x * TW, h0 = blockIdx.y * TH;
    const int b = blockIdx.z;
    const int w = w0 + tdx, h = h0 + tdy;

    // ---- Prologue: stage all 8 planes. Two clamped global offsets per thread
    // (replicate pad folded in once); per plane the loads are [reg + p*PLANE imm].
    const int e0 = tid, e1 = tid + 128;
    const bool has1 = (e1 < SPLN);
    const int goff0 = min(max(h0 - 1 + e0 / SROW, 0), Hh - 1) * Ww
                    + min(max(w0 - 1 + e0 % SROW, 0), Ww - 1);
    const int goff1 = min(max(h0 - 1 + e1 / SROW, 0), Hh - 1) * Ww
                    + min(max(w0 - 1 + e1 % SROW, 0), Ww - 1);
    const float* xb = x + b * Dd * PLANE;

#pragma unroll
    for (int p = 0; p < Dd; p++) {
        sm[p * SPLN + e0] = __ldg(xb + p * PLANE + goff0);
        if (has1) sm[p * SPLN + e1] = __ldg(xb + p * PLANE + goff1);
    }
    __syncthreads();   // the only barrier

    // Thread's 3x3 window top-left within a staged plane.
    const int sbase = tdy * SROW + tdx;

    // load_plane from SMEM (plane index is a compile-time constant after unroll).
#define LOADP(dn, P, cm) do {                                                   \
    const int b_ = (dn) * SPLN + sbase;                                         \
    P[0] = sm[b_];            P[1] = sm[b_ + 1];          P[2] = sm[b_ + 2];    \
    P[3] = sm[b_ + SROW];     P[4] = sm[b_ + SROW + 1];   P[5] = sm[b_ + SROW + 2]; \
    P[6] = sm[b_ + 2*SROW];   P[7] = sm[b_ + 2*SROW + 1]; P[8] = sm[b_ + 2*SROW + 2]; \
    cm[0] = fmaxf(P[0], fmaxf(P[3], P[6]));                                     \
    cm[1] = fmaxf(P[1], fmaxf(P[4], P[7]));                                     \
    cm[2] = fmaxf(P[2], fmaxf(P[5], P[8]));                                     \
} while (0)

    // Rolling window: P0 = plane d-1, C = d, N = d+1, with per-plane column maxima.
    float P0[9], C[9], N[9];
    float cm0[3], cmc[3], cmn[3];

    LOADP(0, C, cmc);
#pragma unroll
    for (int i = 0; i < 9; i++) P0[i] = C[i];
#pragma unroll
    for (int i = 0; i < 3; i++) cm0[i] = cmc[i];       // replicate pad d = -1
    LOADP(1, N, cmn);

    const float wf = (float)w, hf = (float)h;
    const int hw = h * Ww + w;
    float* pD = out + (b * 3 + 0) * Dd * PLANE + hw;
    float* pW = out + (b * 3 + 1) * Dd * PLANE + hw;
    float* pH = out + (b * 3 + 2) * Dd * PLANE + hw;
    float* pY = out + (Bb * 3) * Dd * PLANE + b * Dd * PLANE + hw;

#pragma unroll
    for (int d = 0; d < Dd; d++) {
        const float c = C[4];

        // Separable NMS over the 9 cached column maxima.
        float m = fmaxf(cm0[0], fmaxf(cm0[1], cm0[2]));
        m = fmaxf(m, fmaxf(cmc[0], fmaxf(cmc[1], cmc[2])));
        m = fmaxf(m, fmaxf(cmn[0], fmaxf(cmn[1], cmn[2])));
        const bool nms = (c == m);

        // Gradients (central diff / 2, replicate pad)
        const float gx = 0.5f * (C[5] - C[3]);
        const float gy = 0.5f * (C[7] - C[1]);
        const float gs = 0.5f * (N[4] - P0[4]);

        // Hessian (cross terms * 0.25 per reference)
        const float axx = C[3] + C[5] - 2.0f * c;
        const float ayy = C[1] + C[7] - 2.0f * c;
        const float ass = P0[4] + N[4] - 2.0f * c;
        const float axy = 0.25f * (C[0] + C[8] - C[6] - C[2]);
        const float ays = 0.25f * (P0[1] + N[7] - N[1] - P0[7]);
        const float axs = 0.25f * (P0[3] + N[5] - N[3] - P0[5]);

        // Symmetric 3x3 solve via adjugate (Cramer)
        const float c00 = ayy * ass - ays * ays;
        const float c01 = axs * ays - axy * ass;
        const float c02 = axy * ays - axs * ayy;
        const float det = axx * c00 + axy * c01 + axs * c02;
        const bool keep = nms && (det != 0.0f);

        float rx = 0.0f, ry = 0.0f, rs = 0.0f;
        if (keep) {
            const float inv = 1.0f / det;
            const float c11 = axx * ass - axs * axs;
            const float c12 = axy * axs - axx * ays;
            const float c22 = axx * ayy - axy * axy;
            rx = -(c00 * gx + c01 * gy + c02 * gs) * inv;
            ry = -(c01 * gx + c11 * gy + c12 * gs) * inv;
            rs = -(c02 * gx + c12 * gy + c22 * gs) * inv;
            const float big = fmaxf(fabsf(rx), fmaxf(fabsf(ry), fabsf(rs)));
            if (big > 0.7f) { rx = 0.0f; ry = 0.0f; rs = 0.0f; }
        }

        const float dyv = 0.5f * (gx * rx + gy * ry + gs * rs);
        const float y = c + dyv + (keep ? 10.0f : 0.0f);

        // coords channels: grid(d, w, h) + flipped refinement (s, y, x)
        pD[d * PLANE] = (float)d + rs;
        pW[d * PLANE] = wf + ry;
        pH[d * PLANE] = hf + rx;
        pY[d * PLANE] = y;

        if (d < Dd - 1) {
#pragma unroll
            for (int i = 0; i < 9; i++) { P0[i] = C[i]; C[i] = N[i]; }
#pragma unroll
            for (int i = 0; i < 3; i++) { cm0[i] = cmc[i]; cmc[i] = cmn[i]; }
            const int dn = (d + 2 < Dd) ? d + 2 : Dd - 1;   // replicate pad at d=8
            LOADP(dn, N, cmn);
        }
    }
}

extern "C" void kernel_launch(void* const* d_in, const int* in_sizes, int n_in,
                              void* d_out, int out_size) {
    const float* x = (const float*)d_in[0];
    float* out = (float*)d_out;
    dim3 block(TW, TH, 1);
    dim3 grid(Ww / TW, Hh / TH, Bb);  // (16, 128, 2)
    conv_quad_interp3d_kernel<<<grid, block>>>(x, out);
}